// round 11
// baseline (speedup 1.0000x reference)
#include <cuda_runtime.h>
#include <math.h>
#include <complex>

#ifndef M_PI
#define M_PI 3.14159265358979323846
#endif

#define NB 32
#define NT 300
#define NC 3
#define HW 5184        // 72*72
#define TS 270         // NT - 30
#define WW 29          // window length - 1
#define PAD 18
#define EXT (NT + 2 * PAD)   // 336
#define S33 33               // padded row stride for [i][b] smem arrays
#define NTH_S 256            // k_solve block (255 regs/thread available)
#define NTH_F 256            // k_filt block
#define SWK 10               // sweep chunk (300 = 30*10)
#define FK  8                // filter chunk (336 = 42*8)

// k_solve dynamic smem: sH, sY, sR, sZ = 4 * NT * 33 floats
#define SOLVE_FLOATS (4 * NT * S33)
#define SOLVE_BYTES  (SOLVE_FLOATS * 4)     // 158400
#define SO_H 0
#define SO_Y (NT * S33)
#define SO_R (2 * NT * S33)
#define SO_Z (3 * NT * S33)

// k_filt dynamic smem: sD [NT][33], sC [EXT][33], sF [EXT][33]
#define FILT_FLOATS (NT * S33 + 2 * EXT * S33)
#define FILT_BYTES  (FILT_FLOATS * 4)       // 128304
#define FI_D 0
#define FI_C (NT * S33)
#define FI_F (NT * S33 + EXT * S33)

struct FiltParams {
    float l1[NT];    // LDL^T: L[i,i-1] (unit lower)
    float l2[NT];    // LDL^T: L[i,i-2]
    float invd[NT];  // 1/D[i]
    float fb[6];     // butter numerator
    float fa[6];     // butter denominator (fa[0]=1)
};

// ---------------- scratch (static device globals; no allocation) ----------------
__device__ float g_m[NB * NT * NC];
__device__ float g_Pn[TS * 32 * NB];   // layout [t][w][b], b contiguous
__device__ float g_Hs[NT * NB];        // layout [tau][b]
__device__ float g_d[NT * NB];         // detrended, layout [i][b]

// ---------------- helpers ----------------
__device__ __forceinline__ float wsum(float v) {
#pragma unroll
    for (int o = 16; o; o >>= 1) v += __shfl_xor_sync(0xffffffffu, v, o);
    return v;
}

// ---------------- kernel 1: spatial mean over 72x72 per (b,t,c) ----------------
__global__ void k_mean(const float* __restrict__ x) {
    int s = blockIdx.x;
    const float4* p = reinterpret_cast<const float4*>(x) + (size_t)s * (HW / 4);
    float acc = 0.f;
    for (int i = threadIdx.x; i < HW / 4; i += blockDim.x) {
        float4 v = p[i];
        acc += (v.x + v.y) + (v.z + v.w);
    }
    acc = wsum(acc);
    __shared__ float sh[8];
    int lane = threadIdx.x & 31, wid = threadIdx.x >> 5;
    if (lane == 0) sh[wid] = acc;
    __syncthreads();
    if (threadIdx.x < 8) {
        float v = sh[threadIdx.x];
#pragma unroll
        for (int o = 4; o; o >>= 1) v += __shfl_xor_sync(0xffu, v, o);
        if (threadIdx.x == 0) g_m[s] = v * (1.f / (float)HW);
    }
}

// ---------------- kernel 2: POS per-window -> Pn ([t][w][b] layout) -------------
__global__ void k_pos() {
    int gw = (blockIdx.x * blockDim.x + threadIdx.x) >> 5;
    int lane = threadIdx.x & 31;
    if (gw >= NB * TS) return;
    int b = gw / TS, t = gw - b * TS;

    bool act = lane < WW;
    float c0 = 0.f, c1 = 0.f, c2 = 0.f;
    if (act) {
        const float* p = g_m + ((b * NT) + (t + lane)) * NC;
        c0 = p[0]; c1 = p[1]; c2 = p[2];
    }
    const float invw = 1.0f / (float)WW;
    float mu0 = wsum(c0) * invw;
    float mu1 = wsum(c1) * invw;
    float mu2 = wsum(c2) * invw;
    float n0 = c0 / mu0, n1 = c1 / mu1, n2 = c2 / mu2;
    float s0 = act ? (n1 - n2) : 0.f;
    float s1 = act ? (n1 + n2 - 2.f * n0) : 0.f;
    float m0 = wsum(s0) * invw;
    float m1 = wsum(s1) * invw;
    float d0 = act ? (s0 - m0) : 0.f;
    float d1 = act ? (s1 - m1) : 0.f;
    float v0 = wsum(d0 * d0) * invw;
    float v1 = wsum(d1 * d1) * invw;
    float alpha = sqrtf(v0) / sqrtf(v1);
    float P = s0 + alpha * s1;
    float mp = wsum(act ? P : 0.f) * invw;
    float dp = act ? (P - mp) : 0.f;
    float vp = wsum(dp * dp) * invw;
    float pn = dp / sqrtf(vp);
    g_Pn[(t * 32 + lane) * NB + b] = act ? pn : 0.f;
}

// ---------------- kernel 3: overlap-add gather (full-chip) ----------------------
__global__ void k_hs() {
    int e = blockIdx.x * blockDim.x + threadIdx.x;   // 0..9599
    if (e >= NT * 32) return;
    int b = e & 31, tau = e >> 5;
    int tlo = tau - (WW - 1); if (tlo < 0) tlo = 0;
    int thi = tau; if (thi > TS - 1) thi = TS - 1;
    float s = 0.f;
    for (int t = tlo; t <= thi; t++) s += g_Pn[(31 * t + tau) * NB + b];
    g_Hs[tau * NB + b] = s;
}

// ---------------- kernel 4: detrend IR solve (single block, 256 thr) ------------
__device__ __forceinline__ float A_diag_f(int i) {
    return (i == 0 || i == NT - 1) ? 10001.f : ((i == 1 || i == NT - 2) ? 50001.f : 60001.f);
}
__device__ __forceinline__ float A_e_f(int i) {
    return (i == 1 || i == NT - 1) ? -20000.f : -40000.f;
}

struct FF { float hi, lo; };
__device__ __forceinline__ void ff_sub_prod(FF& s, float a, float y) {
    float p = -a * y;
    float e = fmaf(-a, y, -p);
    float t = s.hi + p;
    float bb = t - s.hi;
    float err = (s.hi - (t - bb)) + (p - bb);
    s.hi = t;
    s.lo += err + e;
}

__global__ void __launch_bounds__(NTH_S) k_solve(FiltParams P) {
    extern __shared__ float sm[];
    float* sH = sm + SO_H;
    float* sY = sm + SO_Y;
    float* sR = sm + SO_R;
    float* sZ = sm + SO_Z;
    __shared__ float2 scF[NT];   // forward:  (l1[i], l2[i])
    __shared__ float2 scB[NT];   // backward: (l1[i+1], l2[i+2])
    __shared__ float  sid[NT];   // invd

    const int tid = threadIdx.x;
    const int lane = tid & 31;
    const int wid = tid >> 5;

    for (int i = tid; i < NT; i += NTH_S) {
        scF[i] = make_float2(P.l1[i], P.l2[i]);
        float l1n = (i + 1 < NT) ? P.l1[i + 1] : 0.f;
        float l2n = (i + 2 < NT) ? P.l2[i + 2] : 0.f;
        scB[i] = make_float2(l1n, l2n);
        sid[i] = P.invd[i];
    }
    for (int e = tid; e < NT * 32; e += NTH_S) {
        float h = g_Hs[e];
        int a = (e >> 5) * S33 + (e & 31);
        sH[a] = h; sR[a] = h; sY[a] = 0.f;
    }
    __syncthreads();

    for (int it = 0; it < 3; it++) {
        if (it > 0) {
            // FF residual r = h - A y  (parallel)
            for (int e = tid; e < NT * 32; e += NTH_S) {
                int b = e & 31, i = e >> 5;
                FF s; s.hi = sH[i * S33 + b]; s.lo = 0.f;
                ff_sub_prod(s, A_diag_f(i), sY[i * S33 + b]);
                if (i >= 1)      ff_sub_prod(s, A_e_f(i),     sY[(i - 1) * S33 + b]);
                if (i <= NT - 2) ff_sub_prod(s, A_e_f(i + 1), sY[(i + 1) * S33 + b]);
                if (i >= 2)      ff_sub_prod(s, 10000.f,      sY[(i - 2) * S33 + b]);
                if (i <= NT - 3) ff_sub_prod(s, 10000.f,      sY[(i + 2) * S33 + b]);
                sR[i * S33 + b] = s.hi + s.lo;
            }
            __syncthreads();
        }
        // forward sweep: warp 0, chunked prefetch (sR -> sZ), float2 coefs
        if (wid == 0) {
            float rr[SWK], nrr[SWK];
            float2 cf[SWK], ncf[SWK];
#pragma unroll
            for (int k = 0; k < SWK; k++) { rr[k] = sR[k * S33 + lane]; cf[k] = scF[k]; }
            float z1 = 0.f, z2 = 0.f;
            for (int c = 0; c < NT / SWK; c++) {
                int base = c * SWK;
                if (c + 1 < NT / SWK) {
#pragma unroll
                    for (int k = 0; k < SWK; k++) {
                        nrr[k] = sR[(base + SWK + k) * S33 + lane];
                        ncf[k] = scF[base + SWK + k];
                    }
                }
#pragma unroll
                for (int k = 0; k < SWK; k++) {
                    float s = fmaf(-cf[k].y, z2, rr[k]);
                    float z = fmaf(-cf[k].x, z1, s);
                    sZ[(base + k) * S33 + lane] = z;
                    z2 = z1; z1 = z;
                }
                if (c + 1 < NT / SWK) {
#pragma unroll
                    for (int k = 0; k < SWK; k++) { rr[k] = nrr[k]; cf[k] = ncf[k]; }
                }
            }
        }
        __syncthreads();
        // diagonal scale (parallel): sZ *= invd
        for (int e = tid; e < NT * 32; e += NTH_S) {
            int b = e & 31, i = e >> 5;
            sZ[i * S33 + b] *= sid[i];
        }
        __syncthreads();
        // backward sweep: warp 0, chunked (sZ -> sR), float2 coefs
        if (wid == 0) {
            float rr[SWK], nrr[SWK];
            float2 cf[SWK], ncf[SWK];
#pragma unroll
            for (int k = 0; k < SWK; k++) {
                int i = NT - 1 - k;
                rr[k] = sZ[i * S33 + lane]; cf[k] = scB[i];
            }
            float c0 = 0.f, c1 = 0.f;
            for (int c = 0; c < NT / SWK; c++) {
                int base = NT - 1 - c * SWK;
                if (c + 1 < NT / SWK) {
#pragma unroll
                    for (int k = 0; k < SWK; k++) {
                        int i = base - SWK - k;
                        nrr[k] = sZ[i * S33 + lane]; ncf[k] = scB[i];
                    }
                }
#pragma unroll
                for (int k = 0; k < SWK; k++) {
                    float s = fmaf(-cf[k].y, c1, rr[k]);
                    float cc = fmaf(-cf[k].x, c0, s);
                    sR[(base - k) * S33 + lane] = cc;
                    c1 = c0; c0 = cc;
                }
                if (c + 1 < NT / SWK) {
#pragma unroll
                    for (int k = 0; k < SWK; k++) { rr[k] = nrr[k]; cf[k] = ncf[k]; }
                }
            }
        }
        __syncthreads();
        // y += c (parallel)
        for (int e = tid; e < NT * 32; e += NTH_S) {
            int b = e & 31, i = e >> 5;
            sY[i * S33 + b] += sR[i * S33 + b];
        }
        __syncthreads();
    }

    // detrended d = h - y -> global
    for (int e = tid; e < NT * 32; e += NTH_S) {
        int b = e & 31, i = e >> 5;
        g_d[i * NB + b] = sH[i * S33 + b] - sY[i * S33 + b];
    }
}

// ---------------- kernel 5: filtfilt + minmax + output (single block, 256 thr) --
__global__ void __launch_bounds__(NTH_F) k_filt(float* __restrict__ out, FiltParams P) {
    extern __shared__ float sm[];
    float* sD = sm + FI_D;   // [NT][33] detrended, then final f
    float* sC = sm + FI_C;   // [EXT][33] ext / pass-1 output
    float* sF = sm + FI_F;   // [EXT][33] FIR scratch
    __shared__ float s_mn[NB], s_inv[NB];

    const int tid = threadIdx.x;
    const int lane = tid & 31;
    const int wid = tid >> 5;

    for (int e = tid; e < NT * 32; e += NTH_F)
        sD[(e >> 5) * S33 + (e & 31)] = g_d[e];
    __syncthreads();

    // build extended signal
    for (int e = tid; e < EXT * 32; e += NTH_F) {
        int b = e & 31, j = e >> 5;
        float v;
        if (j < PAD)            v = 2.f * sD[b] - sD[(PAD - j) * S33 + b];
        else if (j < PAD + NT)  v = sD[(j - PAD) * S33 + b];
        else                    v = 2.f * sD[(NT - 1) * S33 + b] - sD[(NT - 2 - (j - PAD - NT)) * S33 + b];
        sC[j * S33 + b] = v;
    }
    __syncthreads();

    // FIR pass 1
    for (int e = tid; e < EXT * 32; e += NTH_F) {
        int b = e & 31, j = e >> 5;
        float x0 = sC[b];
        float acc = 0.f;
#pragma unroll
        for (int k = 0; k < 6; k++) {
            float xv = (j >= k) ? sC[(j - k) * S33 + b] : x0;
            acc = fmaf(P.fb[k], xv, acc);
        }
        sF[j * S33 + b] = acc;
    }
    __syncthreads();

    // feedback pass 1 (warp 0, chunked): sF -> sC
    if (wid == 0) {
        const float a1 = P.fa[1], a2 = P.fa[2], a3 = P.fa[3], a4 = P.fa[4], a5 = P.fa[5];
        float ff[FK], nf[FK];
        float x0 = sC[lane];
#pragma unroll
        for (int k = 0; k < FK; k++) ff[k] = sF[k * S33 + lane];
        float p1 = x0, p2 = x0, p3 = x0, p4 = x0, p5 = x0;
        for (int c = 0; c < EXT / FK; c++) {
            int base = c * FK;
            if (c + 1 < EXT / FK) {
#pragma unroll
                for (int k = 0; k < FK; k++) nf[k] = sF[(base + FK + k) * S33 + lane];
            }
#pragma unroll
            for (int k = 0; k < FK; k++) {
                float t = fmaf(-a5, p5, ff[k]);
                t = fmaf(-a4, p4, t);
                t = fmaf(-a3, p3, t);
                t = fmaf(-a2, p2, t);
                float yv = fmaf(-a1, p1, t);
                sC[(base + k) * S33 + lane] = yv;
                p5 = p4; p4 = p3; p3 = p2; p2 = p1; p1 = yv;
            }
            if (c + 1 < EXT / FK) {
#pragma unroll
                for (int k = 0; k < FK; k++) ff[k] = nf[k];
            }
        }
    }
    __syncthreads();

    // FIR pass 2 (reversed): sC -> sF
    for (int e = tid; e < EXT * 32; e += NTH_F) {
        int b = e & 31, j = e >> 5;
        float x0b = sC[(EXT - 1) * S33 + b];
        float acc = 0.f;
#pragma unroll
        for (int k = 0; k < 6; k++) {
            float xv = (j >= k) ? sC[(EXT - 1 - j + k) * S33 + b] : x0b;
            acc = fmaf(P.fb[k], xv, acc);
        }
        sF[j * S33 + b] = acc;
    }
    __syncthreads();

    // feedback pass 2 (warp 0, chunked): sF -> f in sD; min/max
    if (wid == 0) {
        const float a1 = P.fa[1], a2 = P.fa[2], a3 = P.fa[3], a4 = P.fa[4], a5 = P.fa[5];
        float ff[FK], nf[FK];
        float x0b = sC[(EXT - 1) * S33 + lane];
#pragma unroll
        for (int k = 0; k < FK; k++) ff[k] = sF[k * S33 + lane];
        float p1 = x0b, p2 = x0b, p3 = x0b, p4 = x0b, p5 = x0b;
        float mn = 3.0e38f, mx = -3.0e38f;
        for (int c = 0; c < EXT / FK; c++) {
            int base = c * FK;
            if (c + 1 < EXT / FK) {
#pragma unroll
                for (int k = 0; k < FK; k++) nf[k] = sF[(base + FK + k) * S33 + lane];
            }
#pragma unroll
            for (int k = 0; k < FK; k++) {
                float t = fmaf(-a5, p5, ff[k]);
                t = fmaf(-a4, p4, t);
                t = fmaf(-a3, p3, t);
                t = fmaf(-a2, p2, t);
                float yv = fmaf(-a1, p1, t);
                int i = (PAD + NT - 1) - (base + k);
                if (i >= 0 && i < NT) {
                    sD[i * S33 + lane] = yv;
                    mn = fminf(mn, yv); mx = fmaxf(mx, yv);
                }
                p5 = p4; p4 = p3; p3 = p2; p2 = p1; p1 = yv;
            }
            if (c + 1 < EXT / FK) {
#pragma unroll
                for (int k = 0; k < FK; k++) ff[k] = nf[k];
            }
        }
        s_mn[lane] = mn;
        s_inv[lane] = 1.f / (mx - mn);
    }
    __syncthreads();

    for (int e = tid; e < NB * NT; e += NTH_F) {
        int b = e / NT, i = e - b * NT;
        out[e] = (sD[i * S33 + b] - s_mn[b]) * s_inv[b];
    }
}

// ---------------- host-side constant computation (capture-time, deterministic) ---
static void compute_params(FiltParams& FP) {
    const double L2 = 10000.0;
    double dgl[NT], e1[NT];
    for (int i = 0; i < NT; i++) {
        double dd = (i == 0 || i == NT - 1) ? 1.0 : ((i == 1 || i == NT - 2) ? 5.0 : 6.0);
        dgl[i] = 1.0 + L2 * dd;
        e1[i]  = (i == 0) ? 0.0 : L2 * ((i == 1 || i == NT - 1) ? -2.0 : -4.0);
    }
    double d[NT], l1[NT], l2[NT];
    l1[0] = 0.0; l2[0] = 0.0; l2[1] = 0.0;
    d[0] = dgl[0];
    l1[1] = e1[1] / d[0];
    d[1] = dgl[1] - l1[1] * l1[1] * d[0];
    for (int i = 2; i < NT; i++) {
        l2[i] = L2 / d[i - 2];
        l1[i] = (e1[i] - l2[i] * l1[i - 1] * d[i - 2]) / d[i - 1];
        d[i] = dgl[i] - l1[i] * l1[i] * d[i - 1] - l2[i] * l2[i] * d[i - 2];
    }
    for (int i = 0; i < NT; i++) {
        FP.l1[i] = (float)l1[i];
        FP.l2[i] = (float)l2[i];
        FP.invd[i] = (float)(1.0 / d[i]);
    }

    using cd = std::complex<double>;
    const int ORD = 5;
    double wn = 3.0 / 15.0;
    double warped = 4.0 * tan(M_PI * wn / 2.0);
    cd p[ORD];
    for (int k = 1; k <= ORD; k++) {
        double ang = M_PI * (2.0 * k + ORD - 1.0) / (2.0 * ORD);
        p[k - 1] = warped * std::exp(cd(0.0, ang));
    }
    double kg = pow(warped, (double)ORD);
    cd pz[ORD];
    cd prod(1.0, 0.0);
    for (int k = 0; k < ORD; k++) {
        pz[k] = (4.0 + p[k]) / (4.0 - p[k]);
        prod *= (4.0 - p[k]);
    }
    double kz = kg * std::real(1.0 / prod);
    const double binom[6] = {1, 5, 10, 10, 5, 1};
    double bcoef[6], acoef[6];
    for (int i = 0; i < 6; i++) bcoef[i] = kz * binom[i];
    cd ac[6];
    ac[0] = cd(1.0, 0.0);
    for (int i = 1; i < 6; i++) ac[i] = cd(0.0, 0.0);
    for (int k = 0; k < ORD; k++)
        for (int j = k + 1; j >= 1; j--) ac[j] = ac[j] - pz[k] * ac[j - 1];
    for (int i = 0; i < 6; i++) acoef[i] = std::real(ac[i]);

    for (int i = 0; i < 6; i++) { FP.fb[i] = (float)bcoef[i]; FP.fa[i] = (float)acoef[i]; }
}

// ---------------- launch ----------------
extern "C" void kernel_launch(void* const* d_in, const int* in_sizes, int n_in,
                              void* d_out, int out_size) {
    const float* x = (const float*)d_in[0];
    float* out = (float*)d_out;

    FiltParams FP;
    compute_params(FP);

    cudaFuncSetAttribute(k_solve, cudaFuncAttributeMaxDynamicSharedMemorySize, SOLVE_BYTES);
    cudaFuncSetAttribute(k_filt,  cudaFuncAttributeMaxDynamicSharedMemorySize, FILT_BYTES);

    k_mean<<<NB * NT * NC, 256>>>(x);
    k_pos<<<(NB * TS * 32 + 127) / 128, 128>>>();
    k_hs<<<(NT * 32 + 127) / 128, 128>>>();
    k_solve<<<1, NTH_S, SOLVE_BYTES>>>(FP);
    k_filt<<<1, NTH_F, FILT_BYTES>>>(out, FP);
}

// round 13
// speedup vs baseline: 1.1613x; 1.1613x over previous
#include <cuda_runtime.h>
#include <math.h>
#include <complex>

#ifndef M_PI
#define M_PI 3.14159265358979323846
#endif

#define NB 32
#define NT 300
#define NC 3
#define HW 5184        // 72*72
#define TS 270         // NT - 30
#define WW 29          // window length - 1
#define PAD 18
#define EXT (NT + 2 * PAD)   // 336
#define S33 33               // padded row stride for [i][b] smem arrays
#define NTH_S 1024           // k_solve block: 32 warps to hide parallel-phase latency
#define NTH_F 1024           // k_filt block
#define SWK 6                // sweep chunk (300 = 50*6), fits 64-reg cap
#define FK  8                // filter chunk (336 = 42*8)
#define NITER 2              // IR iterations (initial solve + 1 refinement)

// k_solve dynamic smem: sH, sY, sR, sZ = 4 * NT * 33 floats
#define SOLVE_FLOATS (4 * NT * S33)
#define SOLVE_BYTES  (SOLVE_FLOATS * 4)     // 158400
#define SO_H 0
#define SO_Y (NT * S33)
#define SO_R (2 * NT * S33)
#define SO_Z (3 * NT * S33)

// k_filt dynamic smem: sD [NT][33], sC [EXT][33], sF [EXT][33]
#define FILT_FLOATS (NT * S33 + 2 * EXT * S33)
#define FILT_BYTES  (FILT_FLOATS * 4)       // 128304
#define FI_D 0
#define FI_C (NT * S33)
#define FI_F (NT * S33 + EXT * S33)

struct FiltParams {
    float l1[NT];    // LDL^T: L[i,i-1] (unit lower)
    float l2[NT];    // LDL^T: L[i,i-2]
    float invd[NT];  // 1/D[i]
    float fb[6];     // butter numerator
    float fa[6];     // butter denominator (fa[0]=1)
};

// ---------------- scratch (static device globals; no allocation) ----------------
__device__ float g_m[NB * NT * NC];
__device__ float g_Pn[TS * 32 * NB];   // layout [t][w][b], b contiguous
__device__ float g_Hs[NT * NB];        // layout [tau][b]
__device__ float g_d[NT * NB];         // detrended, layout [i][b]

// ---------------- helpers ----------------
__device__ __forceinline__ float wsum(float v) {
#pragma unroll
    for (int o = 16; o; o >>= 1) v += __shfl_xor_sync(0xffffffffu, v, o);
    return v;
}

// ---------------- kernel 1: spatial mean over 72x72 per (b,t,c) ----------------
__global__ void k_mean(const float* __restrict__ x) {
    int s = blockIdx.x;
    const float4* p = reinterpret_cast<const float4*>(x) + (size_t)s * (HW / 4);
    float acc = 0.f;
    for (int i = threadIdx.x; i < HW / 4; i += blockDim.x) {
        float4 v = p[i];
        acc += (v.x + v.y) + (v.z + v.w);
    }
    acc = wsum(acc);
    __shared__ float sh[8];
    int lane = threadIdx.x & 31, wid = threadIdx.x >> 5;
    if (lane == 0) sh[wid] = acc;
    __syncthreads();
    if (threadIdx.x < 8) {
        float v = sh[threadIdx.x];
#pragma unroll
        for (int o = 4; o; o >>= 1) v += __shfl_xor_sync(0xffu, v, o);
        if (threadIdx.x == 0) g_m[s] = v * (1.f / (float)HW);
    }
}

// ---------------- kernel 2: POS per-window -> Pn ([t][w][b] layout) -------------
__global__ void k_pos() {
    int gw = (blockIdx.x * blockDim.x + threadIdx.x) >> 5;
    int lane = threadIdx.x & 31;
    if (gw >= NB * TS) return;
    int b = gw / TS, t = gw - b * TS;

    bool act = lane < WW;
    float c0 = 0.f, c1 = 0.f, c2 = 0.f;
    if (act) {
        const float* p = g_m + ((b * NT) + (t + lane)) * NC;
        c0 = p[0]; c1 = p[1]; c2 = p[2];
    }
    const float invw = 1.0f / (float)WW;
    float mu0 = wsum(c0) * invw;
    float mu1 = wsum(c1) * invw;
    float mu2 = wsum(c2) * invw;
    float n0 = c0 / mu0, n1 = c1 / mu1, n2 = c2 / mu2;
    float s0 = act ? (n1 - n2) : 0.f;
    float s1 = act ? (n1 + n2 - 2.f * n0) : 0.f;
    float m0 = wsum(s0) * invw;
    float m1 = wsum(s1) * invw;
    float d0 = act ? (s0 - m0) : 0.f;
    float d1 = act ? (s1 - m1) : 0.f;
    float v0 = wsum(d0 * d0) * invw;
    float v1 = wsum(d1 * d1) * invw;
    float alpha = sqrtf(v0) / sqrtf(v1);
    float P = s0 + alpha * s1;
    float mp = wsum(act ? P : 0.f) * invw;
    float dp = act ? (P - mp) : 0.f;
    float vp = wsum(dp * dp) * invw;
    float pn = dp / sqrtf(vp);
    g_Pn[(t * 32 + lane) * NB + b] = act ? pn : 0.f;
}

// ---------------- kernel 3: overlap-add gather (full-chip) ----------------------
__global__ void k_hs() {
    int e = blockIdx.x * blockDim.x + threadIdx.x;   // 0..9599
    if (e >= NT * 32) return;
    int b = e & 31, tau = e >> 5;
    int tlo = tau - (WW - 1); if (tlo < 0) tlo = 0;
    int thi = tau; if (thi > TS - 1) thi = TS - 1;
    float s = 0.f;
    for (int t = tlo; t <= thi; t++) s += g_Pn[(31 * t + tau) * NB + b];
    g_Hs[tau * NB + b] = s;
}

// ---------------- kernel 4: detrend IR solve (single block, 1024 thr) -----------
__device__ __forceinline__ float A_diag_f(int i) {
    return (i == 0 || i == NT - 1) ? 10001.f : ((i == 1 || i == NT - 2) ? 50001.f : 60001.f);
}
__device__ __forceinline__ float A_e_f(int i) {
    return (i == 1 || i == NT - 1) ? -20000.f : -40000.f;
}

struct FF { float hi, lo; };
__device__ __forceinline__ void ff_sub_prod(FF& s, float a, float y) {
    float p = -a * y;
    float e = fmaf(-a, y, -p);
    float t = s.hi + p;
    float bb = t - s.hi;
    float err = (s.hi - (t - bb)) + (p - bb);
    s.hi = t;
    s.lo += err + e;
}

__global__ void __launch_bounds__(NTH_S) k_solve(FiltParams P) {
    extern __shared__ float sm[];
    float* sH = sm + SO_H;
    float* sY = sm + SO_Y;
    float* sR = sm + SO_R;
    float* sZ = sm + SO_Z;
    __shared__ float2 scF[NT];   // forward:  (l1[i], l2[i])
    __shared__ float2 scB[NT];   // backward: (l1[i+1], l2[i+2])
    __shared__ float  sid[NT];   // invd

    const int tid = threadIdx.x;
    const int lane = tid & 31;
    const int wid = tid >> 5;

    for (int i = tid; i < NT; i += NTH_S) {
        scF[i] = make_float2(P.l1[i], P.l2[i]);
        float l1n = (i + 1 < NT) ? P.l1[i + 1] : 0.f;
        float l2n = (i + 2 < NT) ? P.l2[i + 2] : 0.f;
        scB[i] = make_float2(l1n, l2n);
        sid[i] = P.invd[i];
    }
    for (int e = tid; e < NT * 32; e += NTH_S) {
        float h = g_Hs[e];
        int a = (e >> 5) * S33 + (e & 31);
        sH[a] = h; sR[a] = h; sY[a] = 0.f;
    }
    __syncthreads();

    for (int it = 0; it < NITER; it++) {
        if (it > 0) {
            // FF residual r = h - A y  (parallel across 32 warps)
            for (int e = tid; e < NT * 32; e += NTH_S) {
                int b = e & 31, i = e >> 5;
                FF s; s.hi = sH[i * S33 + b]; s.lo = 0.f;
                ff_sub_prod(s, A_diag_f(i), sY[i * S33 + b]);
                if (i >= 1)      ff_sub_prod(s, A_e_f(i),     sY[(i - 1) * S33 + b]);
                if (i <= NT - 2) ff_sub_prod(s, A_e_f(i + 1), sY[(i + 1) * S33 + b]);
                if (i >= 2)      ff_sub_prod(s, 10000.f,      sY[(i - 2) * S33 + b]);
                if (i <= NT - 3) ff_sub_prod(s, 10000.f,      sY[(i + 2) * S33 + b]);
                sR[i * S33 + b] = s.hi + s.lo;
            }
            __syncthreads();
        }
        // forward sweep: warp 0, chunked prefetch (sR -> sZ)
        if (wid == 0) {
            float rr[SWK], nrr[SWK];
            float2 cf[SWK], ncf[SWK];
#pragma unroll
            for (int k = 0; k < SWK; k++) { rr[k] = sR[k * S33 + lane]; cf[k] = scF[k]; }
            float z1 = 0.f, z2 = 0.f;
            for (int c = 0; c < NT / SWK; c++) {
                int base = c * SWK;
                if (c + 1 < NT / SWK) {
#pragma unroll
                    for (int k = 0; k < SWK; k++) {
                        nrr[k] = sR[(base + SWK + k) * S33 + lane];
                        ncf[k] = scF[base + SWK + k];
                    }
                }
#pragma unroll
                for (int k = 0; k < SWK; k++) {
                    float s = fmaf(-cf[k].y, z2, rr[k]);
                    float z = fmaf(-cf[k].x, z1, s);
                    sZ[(base + k) * S33 + lane] = z;
                    z2 = z1; z1 = z;
                }
                if (c + 1 < NT / SWK) {
#pragma unroll
                    for (int k = 0; k < SWK; k++) { rr[k] = nrr[k]; cf[k] = ncf[k]; }
                }
            }
        }
        __syncthreads();
        // diagonal scale (parallel): sZ *= invd
        for (int e = tid; e < NT * 32; e += NTH_S) {
            int b = e & 31, i = e >> 5;
            sZ[i * S33 + b] *= sid[i];
        }
        __syncthreads();
        // backward sweep: warp 0, chunked (sZ -> sR)
        if (wid == 0) {
            float rr[SWK], nrr[SWK];
            float2 cf[SWK], ncf[SWK];
#pragma unroll
            for (int k = 0; k < SWK; k++) {
                int i = NT - 1 - k;
                rr[k] = sZ[i * S33 + lane]; cf[k] = scB[i];
            }
            float c0 = 0.f, c1 = 0.f;
            for (int c = 0; c < NT / SWK; c++) {
                int base = NT - 1 - c * SWK;
                if (c + 1 < NT / SWK) {
#pragma unroll
                    for (int k = 0; k < SWK; k++) {
                        int i = base - SWK - k;
                        nrr[k] = sZ[i * S33 + lane]; ncf[k] = scB[i];
                    }
                }
#pragma unroll
                for (int k = 0; k < SWK; k++) {
                    float s = fmaf(-cf[k].y, c1, rr[k]);
                    float cc = fmaf(-cf[k].x, c0, s);
                    sR[(base - k) * S33 + lane] = cc;
                    c1 = c0; c0 = cc;
                }
                if (c + 1 < NT / SWK) {
#pragma unroll
                    for (int k = 0; k < SWK; k++) { rr[k] = nrr[k]; cf[k] = ncf[k]; }
                }
            }
        }
        __syncthreads();
        if (it < NITER - 1) {
            // y += c (parallel)
            for (int e = tid; e < NT * 32; e += NTH_S) {
                int b = e & 31, i = e >> 5;
                sY[i * S33 + b] += sR[i * S33 + b];
            }
            __syncthreads();
        } else {
            // final: d = h - (y + c) -> global
            for (int e = tid; e < NT * 32; e += NTH_S) {
                int b = e & 31, i = e >> 5;
                g_d[i * NB + b] = sH[i * S33 + b] - (sY[i * S33 + b] + sR[i * S33 + b]);
            }
        }
    }
}

// ---------------- kernel 5: filtfilt + minmax + output (single block, 1024) -----
__global__ void __launch_bounds__(NTH_F) k_filt(float* __restrict__ out, FiltParams P) {
    extern __shared__ float sm[];
    float* sD = sm + FI_D;   // [NT][33] detrended, then final f
    float* sC = sm + FI_C;   // [EXT][33] ext / pass-1 output
    float* sF = sm + FI_F;   // [EXT][33] FIR scratch
    __shared__ float s_mn[NB], s_inv[NB];

    const int tid = threadIdx.x;
    const int lane = tid & 31;
    const int wid = tid >> 5;

    for (int e = tid; e < NT * 32; e += NTH_F)
        sD[(e >> 5) * S33 + (e & 31)] = g_d[e];
    __syncthreads();

    // build extended signal
    for (int e = tid; e < EXT * 32; e += NTH_F) {
        int b = e & 31, j = e >> 5;
        float v;
        if (j < PAD)            v = 2.f * sD[b] - sD[(PAD - j) * S33 + b];
        else if (j < PAD + NT)  v = sD[(j - PAD) * S33 + b];
        else                    v = 2.f * sD[(NT - 1) * S33 + b] - sD[(NT - 2 - (j - PAD - NT)) * S33 + b];
        sC[j * S33 + b] = v;
    }
    __syncthreads();

    // FIR pass 1
    for (int e = tid; e < EXT * 32; e += NTH_F) {
        int b = e & 31, j = e >> 5;
        float x0 = sC[b];
        float acc = 0.f;
#pragma unroll
        for (int k = 0; k < 6; k++) {
            float xv = (j >= k) ? sC[(j - k) * S33 + b] : x0;
            acc = fmaf(P.fb[k], xv, acc);
        }
        sF[j * S33 + b] = acc;
    }
    __syncthreads();

    // feedback pass 1 (warp 0, chunked): sF -> sC
    if (wid == 0) {
        const float a1 = P.fa[1], a2 = P.fa[2], a3 = P.fa[3], a4 = P.fa[4], a5 = P.fa[5];
        float ff[FK], nf[FK];
        float x0 = sC[lane];
#pragma unroll
        for (int k = 0; k < FK; k++) ff[k] = sF[k * S33 + lane];
        float p1 = x0, p2 = x0, p3 = x0, p4 = x0, p5 = x0;
        for (int c = 0; c < EXT / FK; c++) {
            int base = c * FK;
            if (c + 1 < EXT / FK) {
#pragma unroll
                for (int k = 0; k < FK; k++) nf[k] = sF[(base + FK + k) * S33 + lane];
            }
#pragma unroll
            for (int k = 0; k < FK; k++) {
                float t = fmaf(-a5, p5, ff[k]);
                t = fmaf(-a4, p4, t);
                t = fmaf(-a3, p3, t);
                t = fmaf(-a2, p2, t);
                float yv = fmaf(-a1, p1, t);
                sC[(base + k) * S33 + lane] = yv;
                p5 = p4; p4 = p3; p3 = p2; p2 = p1; p1 = yv;
            }
            if (c + 1 < EXT / FK) {
#pragma unroll
                for (int k = 0; k < FK; k++) ff[k] = nf[k];
            }
        }
    }
    __syncthreads();

    // FIR pass 2 (reversed): sC -> sF
    for (int e = tid; e < EXT * 32; e += NTH_F) {
        int b = e & 31, j = e >> 5;
        float x0b = sC[(EXT - 1) * S33 + b];
        float acc = 0.f;
#pragma unroll
        for (int k = 0; k < 6; k++) {
            float xv = (j >= k) ? sC[(EXT - 1 - j + k) * S33 + b] : x0b;
            acc = fmaf(P.fb[k], xv, acc);
        }
        sF[j * S33 + b] = acc;
    }
    __syncthreads();

    // feedback pass 2 (warp 0, chunked): sF -> f in sD; min/max
    if (wid == 0) {
        const float a1 = P.fa[1], a2 = P.fa[2], a3 = P.fa[3], a4 = P.fa[4], a5 = P.fa[5];
        float ff[FK], nf[FK];
        float x0b = sC[(EXT - 1) * S33 + lane];
#pragma unroll
        for (int k = 0; k < FK; k++) ff[k] = sF[k * S33 + lane];
        float p1 = x0b, p2 = x0b, p3 = x0b, p4 = x0b, p5 = x0b;
        float mn = 3.0e38f, mx = -3.0e38f;
        for (int c = 0; c < EXT / FK; c++) {
            int base = c * FK;
            if (c + 1 < EXT / FK) {
#pragma unroll
                for (int k = 0; k < FK; k++) nf[k] = sF[(base + FK + k) * S33 + lane];
            }
#pragma unroll
            for (int k = 0; k < FK; k++) {
                float t = fmaf(-a5, p5, ff[k]);
                t = fmaf(-a4, p4, t);
                t = fmaf(-a3, p3, t);
                t = fmaf(-a2, p2, t);
                float yv = fmaf(-a1, p1, t);
                int i = (PAD + NT - 1) - (base + k);
                if (i >= 0 && i < NT) {
                    sD[i * S33 + lane] = yv;
                    mn = fminf(mn, yv); mx = fmaxf(mx, yv);
                }
                p5 = p4; p4 = p3; p3 = p2; p2 = p1; p1 = yv;
            }
            if (c + 1 < EXT / FK) {
#pragma unroll
                for (int k = 0; k < FK; k++) ff[k] = nf[k];
            }
        }
        s_mn[lane] = mn;
        s_inv[lane] = 1.f / (mx - mn);
    }
    __syncthreads();

    for (int e = tid; e < NB * NT; e += NTH_F) {
        int b = e / NT, i = e - b * NT;
        out[e] = (sD[i * S33 + b] - s_mn[b]) * s_inv[b];
    }
}

// ---------------- host-side constant computation (capture-time, deterministic) ---
static void compute_params(FiltParams& FP) {
    const double L2 = 10000.0;
    double dgl[NT], e1[NT];
    for (int i = 0; i < NT; i++) {
        double dd = (i == 0 || i == NT - 1) ? 1.0 : ((i == 1 || i == NT - 2) ? 5.0 : 6.0);
        dgl[i] = 1.0 + L2 * dd;
        e1[i]  = (i == 0) ? 0.0 : L2 * ((i == 1 || i == NT - 1) ? -2.0 : -4.0);
    }
    double d[NT], l1[NT], l2[NT];
    l1[0] = 0.0; l2[0] = 0.0; l2[1] = 0.0;
    d[0] = dgl[0];
    l1[1] = e1[1] / d[0];
    d[1] = dgl[1] - l1[1] * l1[1] * d[0];
    for (int i = 2; i < NT; i++) {
        l2[i] = L2 / d[i - 2];
        l1[i] = (e1[i] - l2[i] * l1[i - 1] * d[i - 2]) / d[i - 1];
        d[i] = dgl[i] - l1[i] * l1[i] * d[i - 1] - l2[i] * l2[i] * d[i - 2];
    }
    for (int i = 0; i < NT; i++) {
        FP.l1[i] = (float)l1[i];
        FP.l2[i] = (float)l2[i];
        FP.invd[i] = (float)(1.0 / d[i]);
    }

    using cd = std::complex<double>;
    const int ORD = 5;
    double wn = 3.0 / 15.0;
    double warped = 4.0 * tan(M_PI * wn / 2.0);
    cd p[ORD];
    for (int k = 1; k <= ORD; k++) {
        double ang = M_PI * (2.0 * k + ORD - 1.0) / (2.0 * ORD);
        p[k - 1] = warped * std::exp(cd(0.0, ang));
    }
    double kg = pow(warped, (double)ORD);
    cd pz[ORD];
    cd prod(1.0, 0.0);
    for (int k = 0; k < ORD; k++) {
        pz[k] = (4.0 + p[k]) / (4.0 - p[k]);
        prod *= (4.0 - p[k]);
    }
    double kz = kg * std::real(1.0 / prod);
    const double binom[6] = {1, 5, 10, 10, 5, 1};
    double bcoef[6], acoef[6];
    for (int i = 0; i < 6; i++) bcoef[i] = kz * binom[i];
    cd ac[6];
    ac[0] = cd(1.0, 0.0);
    for (int i = 1; i < 6; i++) ac[i] = cd(0.0, 0.0);
    for (int k = 0; k < ORD; k++)
        for (int j = k + 1; j >= 1; j--) ac[j] = ac[j] - pz[k] * ac[j - 1];
    for (int i = 0; i < 6; i++) acoef[i] = std::real(ac[i]);

    for (int i = 0; i < 6; i++) { FP.fb[i] = (float)bcoef[i]; FP.fa[i] = (float)acoef[i]; }
}

// ---------------- launch ----------------
extern "C" void kernel_launch(void* const* d_in, const int* in_sizes, int n_in,
                              void* d_out, int out_size) {
    const float* x = (const float*)d_in[0];
    float* out = (float*)d_out;

    FiltParams FP;
    compute_params(FP);

    cudaFuncSetAttribute(k_solve, cudaFuncAttributeMaxDynamicSharedMemorySize, SOLVE_BYTES);
    cudaFuncSetAttribute(k_filt,  cudaFuncAttributeMaxDynamicSharedMemorySize, FILT_BYTES);

    k_mean<<<NB * NT * NC, 256>>>(x);
    k_pos<<<(NB * TS * 32 + 127) / 128, 128>>>();
    k_hs<<<(NT * 32 + 127) / 128, 128>>>();
    k_solve<<<1, NTH_S, SOLVE_BYTES>>>(FP);
    k_filt<<<1, NTH_F, FILT_BYTES>>>(out, FP);
}